// round 5
// baseline (speedup 1.0000x reference)
#include <cuda_runtime.h>
#include <cuda_bf16.h>
#include <math.h>

#define NMAX 20000
#define EMAX 320000
#define ETMAX (NMAX + EMAX)
#define DIM 512
#define H1 8
#define C1 64

// ---------------- scratch (static device memory; no allocations) -------------
__device__ float g_bufA[NMAX * DIM];
__device__ float g_bufB[NMAX * DIM];
__device__ float g_bufC[NMAX * DIM];
__device__ float g_bufD[NMAX * DIM];
__device__ float g_als[NMAX * H1];
__device__ float g_ald[NMAX * H1];
__device__ float g_sum[DIM];
__device__ float g_sumsq[DIM];
__device__ int g_cnt[NMAX];
__device__ int g_rowptr[NMAX + 1];
__device__ int g_cursor[NMAX];
__device__ int g_srcs[ETMAX];

// ================= CSR build ==================================================
__global__ void csr_zero(int n) {
    int i = blockIdx.x * blockDim.x + threadIdx.x;
    if (i < n) g_cnt[i] = 0;
}

__global__ void csr_hist(const int* __restrict__ ei, int E, int n) {
    int e = blockIdx.x * blockDim.x + threadIdx.x;
    if (e >= E + n) return;
    int dst = (e < E) ? ei[E + e] : e - E;
    atomicAdd(&g_cnt[dst], 1);
}

__global__ void csr_scan(int n, int Et) {   // single block, 1024 threads
    __shared__ int part[1024];
    int tid = threadIdx.x;
    int chunk = (n + 1023) / 1024;
    int lo = tid * chunk;
    int hi = lo + chunk; if (hi > n) hi = n; if (lo > n) lo = n;
    int s = 0;
    for (int i = lo; i < hi; i++) s += g_cnt[i];
    part[tid] = s;
    __syncthreads();
    for (int off = 1; off < 1024; off <<= 1) {
        int v = (tid >= off) ? part[tid - off] : 0;
        __syncthreads();
        part[tid] += v;
        __syncthreads();
    }
    int run = (tid == 0) ? 0 : part[tid - 1];
    for (int i = lo; i < hi; i++) {
        g_rowptr[i] = run;
        g_cursor[i] = run;
        run += g_cnt[i];
    }
    if (tid == 1023) g_rowptr[n] = Et;
}

__global__ void csr_scatter(const int* __restrict__ ei, int E, int n) {
    int e = blockIdx.x * blockDim.x + threadIdx.x;
    if (e >= E + n) return;
    int src, dst;
    if (e < E) { src = ei[e]; dst = ei[E + e]; }
    else       { src = dst = e - E; }
    int pos = atomicAdd(&g_cursor[dst], 1);
    g_srcs[pos] = src;
}

// ================= BF16x3 compensated tensor-core GEMM ========================
// C[M,N] = A[M,K] @ B[K,N] (+bias)(+relu). N%128==0, K%16==0.
// 128x128 block tile, 8 warps (64x32 warp tile), BK=16, double-buffered smem.
// fp32 operands split into bf16 hi+lo AT SMEM-STORE TIME; inner loop is
// pure LDS + mma.sync.m16n8k16.bf16 (3 passes: hi*hi + hi*lo + lo*hi).

__device__ __forceinline__ void mma_bf16(float* d, const unsigned* a, const unsigned* b) {
    asm volatile(
        "mma.sync.aligned.m16n8k16.row.col.f32.bf16.bf16.f32 "
        "{%0,%1,%2,%3}, {%4,%5,%6,%7}, {%8,%9}, {%0,%1,%2,%3};"
        : "+f"(d[0]), "+f"(d[1]), "+f"(d[2]), "+f"(d[3])
        : "r"(a[0]), "r"(a[1]), "r"(a[2]), "r"(a[3]), "r"(b[0]), "r"(b[1]));
}

__device__ __forceinline__ unsigned pack_hi2(float v0, float v1,
                                             __nv_bfloat16& l0, __nv_bfloat16& l1) {
    __nv_bfloat16 h0 = __float2bfloat16_rn(v0);
    __nv_bfloat16 h1 = __float2bfloat16_rn(v1);
    l0 = __float2bfloat16_rn(v0 - __bfloat162float(h0));
    l1 = __float2bfloat16_rn(v1 - __bfloat162float(h1));
    __nv_bfloat162 p = __halves2bfloat162(h0, h1);   // x = h0 (low), y = h1 (high)
    return *(unsigned*)&p;
}

#define APAD 136   // uint32 row stride for A: (l4*136 + grp) banks all distinct
#define BPAD 12    // uint32 row stride for B: (12*grp + l4) mod 32 all distinct

__global__ __launch_bounds__(256) void gemm_bf16x3(
    const float* __restrict__ A, const float* __restrict__ B,
    const float* __restrict__ bias, float* __restrict__ C,
    int M, int N, int K, int has_bias, int do_relu)
{
    // A tiles: [k2][m] packed bf16x2 along k (k2 = k/2, 0..7)
    __shared__ unsigned AsH[2][8][APAD];
    __shared__ unsigned AsL[2][8][APAD];
    // B tiles: [n][k2] packed bf16x2 along k
    __shared__ unsigned BsH[2][128][BPAD];
    __shared__ unsigned BsL[2][128][BPAD];

    int tid  = threadIdx.x;
    int warp = tid >> 5;
    int lane = tid & 31;
    int grp  = lane >> 2;    // 0..7
    int l4   = lane & 3;     // 0..3

    int m0 = blockIdx.y * 128;
    int n0 = blockIdx.x * 128;
    int wm = (warp >> 2) * 64;   // 0 or 64
    int wn = (warp & 3) * 32;    // 0,32,64,96

    float acc[4][4][4];
#pragma unroll
    for (int mi = 0; mi < 4; mi++)
#pragma unroll
        for (int ni = 0; ni < 4; ni++)
#pragma unroll
            for (int r = 0; r < 4; r++) acc[mi][ni][r] = 0.f;

    // gmem load assignments
    int a_row = tid >> 1;              // 0..127
    int a_k   = (tid & 1) * 8;         // 0 or 8
    int a_k2  = (tid & 1) * 4;         // word row base in AsH/AsL
    int b_k   = tid >> 4;              // 0..15
    int b_k2  = b_k >> 1;
    int b_ko  = b_k & 1;               // halfword select
    int b_n   = (tid & 15) * 8;        // 0..120

    int gm_a = m0 + a_row;
    const float* Arow = A + (size_t)gm_a * K;

    float4 a0v, a1v, b0v, b1v;

    // ---- store helpers (split fp32 -> bf16 hi/lo at smem-store time) ----
#define STORE_A_TILE(BUF)                                                        \
    do {                                                                         \
        __nv_bfloat16 l0, l1;                                                    \
        unsigned h;                                                              \
        h = pack_hi2(a0v.x, a0v.y, l0, l1);                                      \
        AsH[BUF][a_k2 + 0][a_row] = h;                                           \
        { __nv_bfloat162 p = __halves2bfloat162(l0, l1);                         \
          AsL[BUF][a_k2 + 0][a_row] = *(unsigned*)&p; }                          \
        h = pack_hi2(a0v.z, a0v.w, l0, l1);                                      \
        AsH[BUF][a_k2 + 1][a_row] = h;                                           \
        { __nv_bfloat162 p = __halves2bfloat162(l0, l1);                         \
          AsL[BUF][a_k2 + 1][a_row] = *(unsigned*)&p; }                          \
        h = pack_hi2(a1v.x, a1v.y, l0, l1);                                      \
        AsH[BUF][a_k2 + 2][a_row] = h;                                           \
        { __nv_bfloat162 p = __halves2bfloat162(l0, l1);                         \
          AsL[BUF][a_k2 + 2][a_row] = *(unsigned*)&p; }                          \
        h = pack_hi2(a1v.z, a1v.w, l0, l1);                                      \
        AsH[BUF][a_k2 + 3][a_row] = h;                                           \
        { __nv_bfloat162 p = __halves2bfloat162(l0, l1);                         \
          AsL[BUF][a_k2 + 3][a_row] = *(unsigned*)&p; }                          \
    } while (0)

#define STORE_B_TILE(BUF)                                                        \
    do {                                                                         \
        __nv_bfloat16* bh = (__nv_bfloat16*)&BsH[BUF][0][0];                     \
        __nv_bfloat16* bl = (__nv_bfloat16*)&BsL[BUF][0][0];                     \
        float vv[8] = {b0v.x, b0v.y, b0v.z, b0v.w, b1v.x, b1v.y, b1v.z, b1v.w};  \
        _Pragma("unroll")                                                        \
        for (int j = 0; j < 8; j++) {                                            \
            int nn = b_n + j;                                                    \
            __nv_bfloat16 hv = __float2bfloat16_rn(vv[j]);                       \
            __nv_bfloat16 lv = __float2bfloat16_rn(vv[j] - __bfloat162float(hv));\
            int hw = (nn * BPAD + b_k2) * 2 + b_ko;                              \
            bh[hw] = hv;                                                         \
            bl[hw] = lv;                                                         \
        }                                                                        \
    } while (0)

    // ---- preload tile 0 ----
    if (gm_a < M) {
        a0v = *(const float4*)(Arow + a_k);
        a1v = *(const float4*)(Arow + a_k + 4);
    } else {
        a0v = make_float4(0.f, 0.f, 0.f, 0.f);
        a1v = a0v;
    }
    b0v = *(const float4*)(B + (size_t)b_k * N + n0 + b_n);
    b1v = *(const float4*)(B + (size_t)b_k * N + n0 + b_n + 4);
    STORE_A_TILE(0);
    STORE_B_TILE(0);
    __syncthreads();

    int buf = 0;
    for (int k0 = 0; k0 < K; k0 += 16) {
        bool has_next = (k0 + 16) < K;
        if (has_next) {
            if (gm_a < M) {
                a0v = *(const float4*)(Arow + k0 + 16 + a_k);
                a1v = *(const float4*)(Arow + k0 + 16 + a_k + 4);
            } else {
                a0v = make_float4(0.f, 0.f, 0.f, 0.f);
                a1v = a0v;
            }
            b0v = *(const float4*)(B + (size_t)(k0 + 16 + b_k) * N + n0 + b_n);
            b1v = *(const float4*)(B + (size_t)(k0 + 16 + b_k) * N + n0 + b_n + 4);
        }

        // ---- fragment loads (conflict-free) + 48 MMAs ----
        unsigned ah[4][4], al[4][4], bh[4][2], bl[4][2];
#pragma unroll
        for (int mi = 0; mi < 4; mi++) {
            int rm = wm + mi * 16 + grp;
            ah[mi][0] = AsH[buf][l4][rm];
            ah[mi][1] = AsH[buf][l4][rm + 8];
            ah[mi][2] = AsH[buf][l4 + 4][rm];
            ah[mi][3] = AsH[buf][l4 + 4][rm + 8];
            al[mi][0] = AsL[buf][l4][rm];
            al[mi][1] = AsL[buf][l4][rm + 8];
            al[mi][2] = AsL[buf][l4 + 4][rm];
            al[mi][3] = AsL[buf][l4 + 4][rm + 8];
        }
#pragma unroll
        for (int ni = 0; ni < 4; ni++) {
            int nn = wn + ni * 8 + grp;
            bh[ni][0] = BsH[buf][nn][l4];
            bh[ni][1] = BsH[buf][nn][l4 + 4];
            bl[ni][0] = BsL[buf][nn][l4];
            bl[ni][1] = BsL[buf][nn][l4 + 4];
        }
#pragma unroll
        for (int mi = 0; mi < 4; mi++)
#pragma unroll
            for (int ni = 0; ni < 4; ni++) {
                mma_bf16(acc[mi][ni], ah[mi], bh[ni]);
                mma_bf16(acc[mi][ni], ah[mi], bl[ni]);
                mma_bf16(acc[mi][ni], al[mi], bh[ni]);
            }

        if (has_next) {
            __syncthreads();
            int nb = buf ^ 1;
            if (nb) { STORE_A_TILE(1); STORE_B_TILE(1); }
            else    { STORE_A_TILE(0); STORE_B_TILE(0); }
            __syncthreads();
            buf = nb;
        }
    }

    // ---- epilogue ----
#pragma unroll
    for (int mi = 0; mi < 4; mi++) {
        int r0 = m0 + wm + mi * 16 + grp;
        int r1 = r0 + 8;
#pragma unroll
        for (int ni = 0; ni < 4; ni++) {
            int c = n0 + wn + ni * 8 + l4 * 2;
            float2 v0 = make_float2(acc[mi][ni][0], acc[mi][ni][1]);
            float2 v1 = make_float2(acc[mi][ni][2], acc[mi][ni][3]);
            if (has_bias) {
                float2 bv = *(const float2*)(bias + c);
                v0.x += bv.x; v0.y += bv.y;
                v1.x += bv.x; v1.y += bv.y;
            }
            if (do_relu) {
                v0.x = fmaxf(v0.x, 0.f); v0.y = fmaxf(v0.y, 0.f);
                v1.x = fmaxf(v1.x, 0.f); v1.y = fmaxf(v1.y, 0.f);
            }
            if (r0 < M) *(float2*)(C + (size_t)r0 * N + c) = v0;
            if (r1 < M) *(float2*)(C + (size_t)r1 * N + c) = v1;
        }
    }
}

// ================= attention logits ==========================================
__global__ void attn_logits8(const float* __restrict__ h,
                             const float* __restrict__ a_s,
                             const float* __restrict__ a_d,
                             float* __restrict__ als, float* __restrict__ ald, int n)
{
    int node = blockIdx.x;
    if (node >= n) return;
    int w = threadIdx.x >> 5;
    int lane = threadIdx.x & 31;
    const float* row = h + (size_t)node * DIM + w * C1;
    float ss = 0.f, sd = 0.f;
#pragma unroll
    for (int c = lane; c < C1; c += 32) {
        float v = row[c];
        ss = fmaf(v, a_s[w * C1 + c], ss);
        sd = fmaf(v, a_d[w * C1 + c], sd);
    }
#pragma unroll
    for (int o = 16; o; o >>= 1) {
        ss += __shfl_down_sync(0xffffffffu, ss, o);
        sd += __shfl_down_sync(0xffffffffu, sd, o);
    }
    if (lane == 0) { als[node * 8 + w] = ss; ald[node * 8 + w] = sd; }
}

__global__ void attn_logits1(const float* __restrict__ h,
                             const float* __restrict__ a_s,
                             const float* __restrict__ a_d,
                             float* __restrict__ als, float* __restrict__ ald, int n)
{
    int warp = (blockIdx.x * blockDim.x + threadIdx.x) >> 5;
    int lane = threadIdx.x & 31;
    if (warp >= n) return;
    const float* row = h + (size_t)warp * DIM;
    float ss = 0.f, sd = 0.f;
#pragma unroll 4
    for (int c = lane; c < DIM; c += 32) {
        float v = row[c];
        ss = fmaf(v, a_s[c], ss);
        sd = fmaf(v, a_d[c], sd);
    }
#pragma unroll
    for (int o = 16; o; o >>= 1) {
        ss += __shfl_down_sync(0xffffffffu, ss, o);
        sd += __shfl_down_sync(0xffffffffu, sd, o);
    }
    if (lane == 0) { als[warp] = ss; ald[warp] = sd; }
}

// ================= fused GAT softmax+aggregate (CSR, no atomics) ==============
__global__ __launch_bounds__(256) void gat_agg8(
    const float* __restrict__ h, const float* __restrict__ als,
    const float* __restrict__ ald, const float* __restrict__ bias,
    float* __restrict__ out)
{
    int dst = blockIdx.x;
    int hh = threadIdx.x >> 5;
    int lane = threadIdx.x & 31;
    int r0 = g_rowptr[dst], r1 = g_rowptr[dst + 1];
    float aldv = ald[dst * 8 + hh];

    float mx = -1e30f;
    for (int i = r0 + lane; i < r1; i += 32) {
        int s = g_srcs[i];
        float ev = als[s * 8 + hh] + aldv;
        ev = (ev > 0.f) ? ev : 0.2f * ev;
        mx = fmaxf(mx, ev);
    }
#pragma unroll
    for (int o = 16; o; o >>= 1) mx = fmaxf(mx, __shfl_xor_sync(0xffffffffu, mx, o));

    float sum = 0.f;
    for (int i = r0 + lane; i < r1; i += 32) {
        int s = g_srcs[i];
        float ev = als[s * 8 + hh] + aldv;
        ev = (ev > 0.f) ? ev : 0.2f * ev;
        sum += __expf(ev - mx);
    }
#pragma unroll
    for (int o = 16; o; o >>= 1) sum += __shfl_xor_sync(0xffffffffu, sum, o);
    float inv_s = 1.f / sum;

    int c = hh * 64 + lane * 2;
    float2 acc = make_float2(0.f, 0.f);
    for (int i = r0; i < r1; i++) {
        int s = g_srcs[i];
        float ev = als[s * 8 + hh] + aldv;
        ev = (ev > 0.f) ? ev : 0.2f * ev;
        float w = __expf(ev - mx) * inv_s;
        float2 v = *(const float2*)(h + (size_t)s * DIM + c);
        acc.x = fmaf(w, v.x, acc.x);
        acc.y = fmaf(w, v.y, acc.y);
    }
    float2 bv = *(const float2*)(bias + c);
    acc.x += bv.x; acc.y += bv.y;
    *(float2*)(out + (size_t)dst * DIM + c) = acc;
}

__global__ __launch_bounds__(256) void gat_agg1(
    const float* __restrict__ h, const float* __restrict__ als,
    const float* __restrict__ ald, const float* __restrict__ bias,
    float* __restrict__ out)
{
    __shared__ float sh_mx, sh_inv;
    int dst = blockIdx.x;
    int tid = threadIdx.x;
    int r0 = g_rowptr[dst], r1 = g_rowptr[dst + 1];
    float aldv = ald[dst];

    if (tid < 32) {
        float mx = -1e30f;
        for (int i = r0 + tid; i < r1; i += 32) {
            int s = g_srcs[i];
            float ev = als[s] + aldv;
            ev = (ev > 0.f) ? ev : 0.2f * ev;
            mx = fmaxf(mx, ev);
        }
#pragma unroll
        for (int o = 16; o; o >>= 1) mx = fmaxf(mx, __shfl_xor_sync(0xffffffffu, mx, o));
        float sum = 0.f;
        for (int i = r0 + tid; i < r1; i += 32) {
            int s = g_srcs[i];
            float ev = als[s] + aldv;
            ev = (ev > 0.f) ? ev : 0.2f * ev;
            sum += __expf(ev - mx);
        }
#pragma unroll
        for (int o = 16; o; o >>= 1) sum += __shfl_xor_sync(0xffffffffu, sum, o);
        if (tid == 0) { sh_mx = mx; sh_inv = 1.f / sum; }
    }
    __syncthreads();
    float mx = sh_mx, inv_s = sh_inv;

    int c = tid * 2;
    float2 acc = make_float2(0.f, 0.f);
    for (int i = r0; i < r1; i++) {
        int s = g_srcs[i];
        float ev = als[s] + aldv;
        ev = (ev > 0.f) ? ev : 0.2f * ev;
        float w = __expf(ev - mx) * inv_s;
        float2 v = *(const float2*)(h + (size_t)s * DIM + c);
        acc.x = fmaf(w, v.x, acc.x);
        acc.y = fmaf(w, v.y, acc.y);
    }
    float2 bv = *(const float2*)(bias + c);
    acc.x += bv.x; acc.y += bv.y;
    *(float2*)(out + (size_t)dst * DIM + c) = acc;
}

// ================= BN =========================================================
__global__ void zero_stats() {
    int i = threadIdx.x;
    if (i < DIM) { g_sum[i] = 0.f; g_sumsq[i] = 0.f; }
}

__global__ void bn_stats(const float* __restrict__ x, int n)
{
    int col = blockIdx.x * 256 + threadIdx.x;   // gridDim.x == 2
    float sm = 0.f, sq = 0.f;
    for (int r = blockIdx.y; r < n; r += gridDim.y) {
        float v = x[(size_t)r * DIM + col];
        sm += v;
        sq = fmaf(v, v, sq);
    }
    atomicAdd(&g_sum[col], sm);
    atomicAdd(&g_sumsq[col], sq);
}

__global__ void bn_apply(const float* __restrict__ x,
                         const float* __restrict__ gamma, const float* __restrict__ beta,
                         float* __restrict__ y, int n)
{
    int i = blockIdx.x * blockDim.x + threadIdx.x;
    if (i >= n * DIM) return;
    int col = i & (DIM - 1);
    float inv_n = 1.f / (float)n;
    float mu = g_sum[col] * inv_n;
    float var = g_sumsq[col] * inv_n - mu * mu;
    y[i] = fmaf(gamma[col] * (x[i] - mu), rsqrtf(var + 1e-5f), beta[col]);
}

// ================= final linear [512 -> 2] + relu =============================
__global__ void final_lin(const float* __restrict__ h, const float* __restrict__ w,
                          const float* __restrict__ b, float* __restrict__ out, int n)
{
    int warp = (blockIdx.x * blockDim.x + threadIdx.x) >> 5;
    int lane = threadIdx.x & 31;
    if (warp >= n) return;
    const float* row = h + (size_t)warp * DIM;
    float a0 = 0.f, a1 = 0.f;
#pragma unroll 4
    for (int c = lane; c < DIM; c += 32) {
        float v = row[c];
        a0 = fmaf(v, w[c * 2 + 0], a0);
        a1 = fmaf(v, w[c * 2 + 1], a1);
    }
#pragma unroll
    for (int o = 16; o; o >>= 1) {
        a0 += __shfl_down_sync(0xffffffffu, a0, o);
        a1 += __shfl_down_sync(0xffffffffu, a1, o);
    }
    if (lane == 0) {
        out[warp * 2 + 0] = fmaxf(a0 + b[0], 0.f);
        out[warp * 2 + 1] = fmaxf(a1 + b[1], 0.f);
    }
}

// ------------------------------------------------------------------------------
extern "C" void kernel_launch(void* const* d_in, const int* in_sizes, int n_in,
                              void* d_out, int out_size)
{
    const float* x    = (const float*)d_in[0];
    const int*   ei   = (const int*)d_in[1];     // int32 edge indices
    const float* W1   = (const float*)d_in[2];
    const float* a1s  = (const float*)d_in[3];
    const float* a1d  = (const float*)d_in[4];
    const float* b1   = (const float*)d_in[5];
    const float* W2   = (const float*)d_in[6];
    const float* a2s  = (const float*)d_in[7];
    const float* a2d  = (const float*)d_in[8];
    const float* b2   = (const float*)d_in[9];
    const float* fc1w = (const float*)d_in[10];
    const float* fc1b = (const float*)d_in[11];
    const float* g1   = (const float*)d_in[12];
    const float* be1  = (const float*)d_in[13];
    const float* fc2w = (const float*)d_in[14];
    const float* fc2b = (const float*)d_in[15];
    const float* g2   = (const float*)d_in[16];
    const float* be2  = (const float*)d_in[17];
    const float* linw = (const float*)d_in[18];
    const float* linb = (const float*)d_in[19];
    float* out = (float*)d_out;

    int n = out_size / 2;        // 20000
    int E = in_sizes[1] / 2;     // 320000
    int Et = E + n;

    float *A, *B, *C, *Dd, *als, *ald;
    cudaGetSymbolAddress((void**)&A,   g_bufA);
    cudaGetSymbolAddress((void**)&B,   g_bufB);
    cudaGetSymbolAddress((void**)&C,   g_bufC);
    cudaGetSymbolAddress((void**)&Dd,  g_bufD);
    cudaGetSymbolAddress((void**)&als, g_als);
    cudaGetSymbolAddress((void**)&ald, g_ald);

    dim3 gemm_grid(DIM / 128, (n + 127) / 128);
    int nd_blocks = (n * DIM + 255) / 256;

    // ---------------- CSR build (once, reused by both layers) ----------------
    csr_zero<<<(n + 255) / 256, 256>>>(n);
    csr_hist<<<(Et + 255) / 256, 256>>>(ei, E, n);
    csr_scan<<<1, 1024>>>(n, Et);
    csr_scatter<<<(Et + 255) / 256, 256>>>(ei, E, n);

    // ---------------- layer 1: GATConv(128 -> 8x64) ----------------
    gemm_bf16x3<<<gemm_grid, 256>>>(x, W1, nullptr, A, n, DIM, 128, 0, 0);
    attn_logits8<<<n, 256>>>(A, a1s, a1d, als, ald, n);
    gat_agg8<<<n, 256>>>(A, als, ald, b1, B);

    // ---------------- fc1 + relu + BN ----------------
    gemm_bf16x3<<<gemm_grid, 256>>>(B, fc1w, fc1b, C, n, DIM, DIM, 1, 1);
    zero_stats<<<1, 512>>>();
    bn_stats<<<dim3(2, 128), 256>>>(C, n);
    bn_apply<<<nd_blocks, 256>>>(C, g1, be1, Dd, n);

    // ---------------- layer 2: GATConv(512 -> 1x512) ----------------
    gemm_bf16x3<<<gemm_grid, 256>>>(Dd, W2, nullptr, A, n, DIM, DIM, 0, 0);
    attn_logits1<<<(n + 7) / 8, 256>>>(A, a2s, a2d, als, ald, n);
    gat_agg1<<<n, 256>>>(A, als, ald, b2, B);

    // ---------------- fc2 + relu + BN ----------------
    gemm_bf16x3<<<gemm_grid, 256>>>(B, fc2w, fc2b, C, n, DIM, DIM, 1, 1);
    zero_stats<<<1, 512>>>();
    bn_stats<<<dim3(2, 128), 256>>>(C, n);
    bn_apply<<<nd_blocks, 256>>>(C, g2, be2, Dd, n);

    // ---------------- final linear + relu ----------------
    final_lin<<<(n * 32 + 255) / 256, 256>>>(Dd, linw, linb, out, n);
}

// round 6
// speedup vs baseline: 1.6943x; 1.6943x over previous
#include <cuda_runtime.h>
#include <cuda_bf16.h>
#include <math.h>

#define NMAX 20000
#define EMAX 320000
#define ETMAX (NMAX + EMAX)
#define DIM 512
#define H1 8
#define C1 64

// ---------------- scratch (static device memory; no allocations) -------------
__device__ float g_bufA[NMAX * DIM];
__device__ float g_bufB[NMAX * DIM];
__device__ float g_bufC[NMAX * DIM];
__device__ float g_bufD[NMAX * DIM];
__device__ float g_als[NMAX * H1];
__device__ float g_ald[NMAX * H1];
__device__ float g_sum[DIM];
__device__ float g_sumsq[DIM];
__device__ int g_cnt[NMAX];
__device__ int g_rowptr[NMAX + 1];
__device__ int g_cursor[NMAX];
__device__ int g_srcs[ETMAX];

// ================= CSR build ==================================================
__global__ void csr_zero(int n) {
    int i = blockIdx.x * blockDim.x + threadIdx.x;
    if (i < n) g_cnt[i] = 0;
}

__global__ void csr_hist(const int* __restrict__ ei, int E, int n) {
    int e = blockIdx.x * blockDim.x + threadIdx.x;
    if (e >= E + n) return;
    int dst = (e < E) ? ei[E + e] : e - E;
    atomicAdd(&g_cnt[dst], 1);
}

__global__ void csr_scan(int n, int Et) {   // single block, 1024 threads
    __shared__ int part[1024];
    int tid = threadIdx.x;
    int chunk = (n + 1023) / 1024;
    int lo = tid * chunk;
    int hi = lo + chunk; if (hi > n) hi = n; if (lo > n) lo = n;
    int s = 0;
    for (int i = lo; i < hi; i++) s += g_cnt[i];
    part[tid] = s;
    __syncthreads();
    for (int off = 1; off < 1024; off <<= 1) {
        int v = (tid >= off) ? part[tid - off] : 0;
        __syncthreads();
        part[tid] += v;
        __syncthreads();
    }
    int run = (tid == 0) ? 0 : part[tid - 1];
    for (int i = lo; i < hi; i++) {
        g_rowptr[i] = run;
        g_cursor[i] = run;
        run += g_cnt[i];
    }
    if (tid == 1023) g_rowptr[n] = Et;
}

__global__ void csr_scatter(const int* __restrict__ ei, int E, int n) {
    int e = blockIdx.x * blockDim.x + threadIdx.x;
    if (e >= E + n) return;
    int src, dst;
    if (e < E) { src = ei[e]; dst = ei[E + e]; }
    else       { src = dst = e - E; }
    int pos = atomicAdd(&g_cursor[dst], 1);
    g_srcs[pos] = src;
}

// ================= BF16x3 compensated tensor-core GEMM ========================
// C[M,N] = A[M,K] @ B[K,N] (+bias)(+relu). N%128==0, K%16==0.
// 128x128 block tile, 8 warps (64x32 warp tile), BK=16, double-buffered smem.
// fp32 split into bf16 hi+lo at smem-store time; tiles stored as packed
// bf16x2-along-k words in [k2][PAD] layout (conflict-free fragment reads,
// uint4 B stores). Inner loop: pure LDS + mma.sync.m16n8k16.bf16 x3.

__device__ __forceinline__ void mma_bf16(float* d, const unsigned* a, const unsigned* b) {
    asm volatile(
        "mma.sync.aligned.m16n8k16.row.col.f32.bf16.bf16.f32 "
        "{%0,%1,%2,%3}, {%4,%5,%6,%7}, {%8,%9}, {%0,%1,%2,%3};"
        : "+f"(d[0]), "+f"(d[1]), "+f"(d[2]), "+f"(d[3])
        : "r"(a[0]), "r"(a[1]), "r"(a[2]), "r"(a[3]), "r"(b[0]), "r"(b[1]));
}

// split two fp32 (consecutive k) into packed bf16x2 hi word + lo word
__device__ __forceinline__ void split_pack2(float v0, float v1,
                                            unsigned& hw, unsigned& lw) {
    __nv_bfloat16 h0 = __float2bfloat16_rn(v0);
    __nv_bfloat16 h1 = __float2bfloat16_rn(v1);
    __nv_bfloat16 l0 = __float2bfloat16_rn(v0 - __bfloat162float(h0));
    __nv_bfloat16 l1 = __float2bfloat16_rn(v1 - __bfloat162float(h1));
    __nv_bfloat162 hp = __halves2bfloat162(h0, h1);
    __nv_bfloat162 lp = __halves2bfloat162(l0, l1);
    hw = *(unsigned*)&hp;
    lw = *(unsigned*)&lp;
}

#define TPAD 136   // word stride: bank = (8*l4 + idx) -> all 32 distinct

__global__ __launch_bounds__(256) void gemm_bf16x3(
    const float* __restrict__ A, const float* __restrict__ B,
    const float* __restrict__ bias, float* __restrict__ C,
    int M, int N, int K, int has_bias, int do_relu)
{
    // [buf][k2][m or n] packed bf16x2-along-k words
    __shared__ unsigned AsH[2][8][TPAD];
    __shared__ unsigned AsL[2][8][TPAD];
    __shared__ unsigned BsH[2][8][TPAD];
    __shared__ unsigned BsL[2][8][TPAD];

    int tid  = threadIdx.x;
    int warp = tid >> 5;
    int lane = tid & 31;
    int grp  = lane >> 2;    // 0..7
    int l4   = lane & 3;     // 0..3

    int m0 = blockIdx.y * 128;
    int n0 = blockIdx.x * 128;
    int wm = (warp >> 2) * 64;   // 0 or 64
    int wn = (warp & 3) * 32;    // 0,32,64,96

    float acc[4][4][4];
#pragma unroll
    for (int mi = 0; mi < 4; mi++)
#pragma unroll
        for (int ni = 0; ni < 4; ni++)
#pragma unroll
            for (int r = 0; r < 4; r++) acc[mi][ni][r] = 0.f;

    // A gmem: thread loads 8 consecutive k of one m-row
    int a_row = tid >> 1;              // 0..127
    int a_k   = (tid & 1) * 8;         // 0 or 8
    int a_k2  = (tid & 1) * 4;         // word row base
    // B gmem: warp w loads k rows {2w, 2w+1}, lane covers 4 n-columns
    int b_k0  = warp * 2;
    int b_n   = lane * 4;

    int gm_a = m0 + a_row;
    const float* Arow = A + (size_t)gm_a * K;

    float4 a0v, a1v, b0v, b1v;

    // ---- preload tile 0 ----
    if (gm_a < M) {
        a0v = *(const float4*)(Arow + a_k);
        a1v = *(const float4*)(Arow + a_k + 4);
    } else {
        a0v = make_float4(0.f, 0.f, 0.f, 0.f);
        a1v = a0v;
    }
    b0v = *(const float4*)(B + (size_t)b_k0 * N + n0 + b_n);
    b1v = *(const float4*)(B + (size_t)(b_k0 + 1) * N + n0 + b_n);

    {
        unsigned hw, lw;
        split_pack2(a0v.x, a0v.y, hw, lw); AsH[0][a_k2 + 0][a_row] = hw; AsL[0][a_k2 + 0][a_row] = lw;
        split_pack2(a0v.z, a0v.w, hw, lw); AsH[0][a_k2 + 1][a_row] = hw; AsL[0][a_k2 + 1][a_row] = lw;
        split_pack2(a1v.x, a1v.y, hw, lw); AsH[0][a_k2 + 2][a_row] = hw; AsL[0][a_k2 + 2][a_row] = lw;
        split_pack2(a1v.z, a1v.w, hw, lw); AsH[0][a_k2 + 3][a_row] = hw; AsL[0][a_k2 + 3][a_row] = lw;
        uint4 bh, bl;
        split_pack2(b0v.x, b1v.x, bh.x, bl.x);
        split_pack2(b0v.y, b1v.y, bh.y, bl.y);
        split_pack2(b0v.z, b1v.z, bh.z, bl.z);
        split_pack2(b0v.w, b1v.w, bh.w, bl.w);
        *(uint4*)&BsH[0][warp][b_n] = bh;
        *(uint4*)&BsL[0][warp][b_n] = bl;
    }
    __syncthreads();

    int buf = 0;
    for (int k0 = 0; k0 < K; k0 += 16) {
        bool has_next = (k0 + 16) < K;
        if (has_next) {
            if (gm_a < M) {
                a0v = *(const float4*)(Arow + k0 + 16 + a_k);
                a1v = *(const float4*)(Arow + k0 + 16 + a_k + 4);
            } else {
                a0v = make_float4(0.f, 0.f, 0.f, 0.f);
                a1v = a0v;
            }
            b0v = *(const float4*)(B + (size_t)(k0 + 16 + b_k0) * N + n0 + b_n);
            b1v = *(const float4*)(B + (size_t)(k0 + 16 + b_k0 + 1) * N + n0 + b_n);
        }

        // ---- fragment loads (conflict-free) + 48 MMAs ----
        unsigned ah[4][4], al[4][4], bh[4][2], bl[4][2];
#pragma unroll
        for (int mi = 0; mi < 4; mi++) {
            int rm = wm + mi * 16 + grp;
            ah[mi][0] = AsH[buf][l4][rm];
            ah[mi][1] = AsH[buf][l4][rm + 8];
            ah[mi][2] = AsH[buf][l4 + 4][rm];
            ah[mi][3] = AsH[buf][l4 + 4][rm + 8];
            al[mi][0] = AsL[buf][l4][rm];
            al[mi][1] = AsL[buf][l4][rm + 8];
            al[mi][2] = AsL[buf][l4 + 4][rm];
            al[mi][3] = AsL[buf][l4 + 4][rm + 8];
        }
#pragma unroll
        for (int ni = 0; ni < 4; ni++) {
            int nn = wn + ni * 8 + grp;
            bh[ni][0] = BsH[buf][l4][nn];
            bh[ni][1] = BsH[buf][l4 + 4][nn];
            bl[ni][0] = BsL[buf][l4][nn];
            bl[ni][1] = BsL[buf][l4 + 4][nn];
        }
#pragma unroll
        for (int mi = 0; mi < 4; mi++)
#pragma unroll
            for (int ni = 0; ni < 4; ni++) {
                mma_bf16(acc[mi][ni], ah[mi], bh[ni]);
                mma_bf16(acc[mi][ni], ah[mi], bl[ni]);
                mma_bf16(acc[mi][ni], al[mi], bh[ni]);
            }

        if (has_next) {
            __syncthreads();
            int nb = buf ^ 1;
            unsigned hw, lw;
            split_pack2(a0v.x, a0v.y, hw, lw); AsH[nb][a_k2 + 0][a_row] = hw; AsL[nb][a_k2 + 0][a_row] = lw;
            split_pack2(a0v.z, a0v.w, hw, lw); AsH[nb][a_k2 + 1][a_row] = hw; AsL[nb][a_k2 + 1][a_row] = lw;
            split_pack2(a1v.x, a1v.y, hw, lw); AsH[nb][a_k2 + 2][a_row] = hw; AsL[nb][a_k2 + 2][a_row] = lw;
            split_pack2(a1v.z, a1v.w, hw, lw); AsH[nb][a_k2 + 3][a_row] = hw; AsL[nb][a_k2 + 3][a_row] = lw;
            uint4 nbh, nbl;
            split_pack2(b0v.x, b1v.x, nbh.x, nbl.x);
            split_pack2(b0v.y, b1v.y, nbh.y, nbl.y);
            split_pack2(b0v.z, b1v.z, nbh.z, nbl.z);
            split_pack2(b0v.w, b1v.w, nbh.w, nbl.w);
            *(uint4*)&BsH[nb][warp][b_n] = nbh;
            *(uint4*)&BsL[nb][warp][b_n] = nbl;
            __syncthreads();
            buf = nb;
        }
    }

    // ---- epilogue ----
#pragma unroll
    for (int mi = 0; mi < 4; mi++) {
        int r0 = m0 + wm + mi * 16 + grp;
        int r1 = r0 + 8;
#pragma unroll
        for (int ni = 0; ni < 4; ni++) {
            int c = n0 + wn + ni * 8 + l4 * 2;
            float2 v0 = make_float2(acc[mi][ni][0], acc[mi][ni][1]);
            float2 v1 = make_float2(acc[mi][ni][2], acc[mi][ni][3]);
            if (has_bias) {
                float2 bv = *(const float2*)(bias + c);
                v0.x += bv.x; v0.y += bv.y;
                v1.x += bv.x; v1.y += bv.y;
            }
            if (do_relu) {
                v0.x = fmaxf(v0.x, 0.f); v0.y = fmaxf(v0.y, 0.f);
                v1.x = fmaxf(v1.x, 0.f); v1.y = fmaxf(v1.y, 0.f);
            }
            if (r0 < M) *(float2*)(C + (size_t)r0 * N + c) = v0;
            if (r1 < M) *(float2*)(C + (size_t)r1 * N + c) = v1;
        }
    }
}

// ================= attention logits ==========================================
__global__ void attn_logits8(const float* __restrict__ h,
                             const float* __restrict__ a_s,
                             const float* __restrict__ a_d,
                             float* __restrict__ als, float* __restrict__ ald, int n)
{
    int node = blockIdx.x;
    if (node >= n) return;
    int w = threadIdx.x >> 5;
    int lane = threadIdx.x & 31;
    const float* row = h + (size_t)node * DIM + w * C1;
    float ss = 0.f, sd = 0.f;
#pragma unroll
    for (int c = lane; c < C1; c += 32) {
        float v = row[c];
        ss = fmaf(v, a_s[w * C1 + c], ss);
        sd = fmaf(v, a_d[w * C1 + c], sd);
    }
#pragma unroll
    for (int o = 16; o; o >>= 1) {
        ss += __shfl_down_sync(0xffffffffu, ss, o);
        sd += __shfl_down_sync(0xffffffffu, sd, o);
    }
    if (lane == 0) { als[node * 8 + w] = ss; ald[node * 8 + w] = sd; }
}

__global__ void attn_logits1(const float* __restrict__ h,
                             const float* __restrict__ a_s,
                             const float* __restrict__ a_d,
                             float* __restrict__ als, float* __restrict__ ald, int n)
{
    int warp = (blockIdx.x * blockDim.x + threadIdx.x) >> 5;
    int lane = threadIdx.x & 31;
    if (warp >= n) return;
    const float* row = h + (size_t)warp * DIM;
    float ss = 0.f, sd = 0.f;
#pragma unroll 4
    for (int c = lane; c < DIM; c += 32) {
        float v = row[c];
        ss = fmaf(v, a_s[c], ss);
        sd = fmaf(v, a_d[c], sd);
    }
#pragma unroll
    for (int o = 16; o; o >>= 1) {
        ss += __shfl_down_sync(0xffffffffu, ss, o);
        sd += __shfl_down_sync(0xffffffffu, sd, o);
    }
    if (lane == 0) { als[warp] = ss; ald[warp] = sd; }
}

// ================= fused GAT softmax+aggregate (CSR, no atomics) ==============
__global__ __launch_bounds__(256) void gat_agg8(
    const float* __restrict__ h, const float* __restrict__ als,
    const float* __restrict__ ald, const float* __restrict__ bias,
    float* __restrict__ out)
{
    int dst = blockIdx.x;
    int hh = threadIdx.x >> 5;
    int lane = threadIdx.x & 31;
    int r0 = g_rowptr[dst], r1 = g_rowptr[dst + 1];
    float aldv = ald[dst * 8 + hh];

    float mx = -1e30f;
    for (int i = r0 + lane; i < r1; i += 32) {
        int s = g_srcs[i];
        float ev = als[s * 8 + hh] + aldv;
        ev = (ev > 0.f) ? ev : 0.2f * ev;
        mx = fmaxf(mx, ev);
    }
#pragma unroll
    for (int o = 16; o; o >>= 1) mx = fmaxf(mx, __shfl_xor_sync(0xffffffffu, mx, o));

    float sum = 0.f;
    for (int i = r0 + lane; i < r1; i += 32) {
        int s = g_srcs[i];
        float ev = als[s * 8 + hh] + aldv;
        ev = (ev > 0.f) ? ev : 0.2f * ev;
        sum += __expf(ev - mx);
    }
#pragma unroll
    for (int o = 16; o; o >>= 1) sum += __shfl_xor_sync(0xffffffffu, sum, o);
    float inv_s = 1.f / sum;

    int c = hh * 64 + lane * 2;
    float2 acc = make_float2(0.f, 0.f);
    for (int i = r0; i < r1; i++) {
        int s = g_srcs[i];
        float ev = als[s * 8 + hh] + aldv;
        ev = (ev > 0.f) ? ev : 0.2f * ev;
        float w = __expf(ev - mx) * inv_s;
        float2 v = *(const float2*)(h + (size_t)s * DIM + c);
        acc.x = fmaf(w, v.x, acc.x);
        acc.y = fmaf(w, v.y, acc.y);
    }
    float2 bv = *(const float2*)(bias + c);
    acc.x += bv.x; acc.y += bv.y;
    *(float2*)(out + (size_t)dst * DIM + c) = acc;
}

__global__ __launch_bounds__(256) void gat_agg1(
    const float* __restrict__ h, const float* __restrict__ als,
    const float* __restrict__ ald, const float* __restrict__ bias,
    float* __restrict__ out)
{
    __shared__ float sh_mx, sh_inv;
    int dst = blockIdx.x;
    int tid = threadIdx.x;
    int r0 = g_rowptr[dst], r1 = g_rowptr[dst + 1];
    float aldv = ald[dst];

    if (tid < 32) {
        float mx = -1e30f;
        for (int i = r0 + tid; i < r1; i += 32) {
            int s = g_srcs[i];
            float ev = als[s] + aldv;
            ev = (ev > 0.f) ? ev : 0.2f * ev;
            mx = fmaxf(mx, ev);
        }
#pragma unroll
        for (int o = 16; o; o >>= 1) mx = fmaxf(mx, __shfl_xor_sync(0xffffffffu, mx, o));
        float sum = 0.f;
        for (int i = r0 + tid; i < r1; i += 32) {
            int s = g_srcs[i];
            float ev = als[s] + aldv;
            ev = (ev > 0.f) ? ev : 0.2f * ev;
            sum += __expf(ev - mx);
        }
#pragma unroll
        for (int o = 16; o; o >>= 1) sum += __shfl_xor_sync(0xffffffffu, sum, o);
        if (tid == 0) { sh_mx = mx; sh_inv = 1.f / sum; }
    }
    __syncthreads();
    float mx = sh_mx, inv_s = sh_inv;

    int c = tid * 2;
    float2 acc = make_float2(0.f, 0.f);
    for (int i = r0; i < r1; i++) {
        int s = g_srcs[i];
        float ev = als[s] + aldv;
        ev = (ev > 0.f) ? ev : 0.2f * ev;
        float w = __expf(ev - mx) * inv_s;
        float2 v = *(const float2*)(h + (size_t)s * DIM + c);
        acc.x = fmaf(w, v.x, acc.x);
        acc.y = fmaf(w, v.y, acc.y);
    }
    float2 bv = *(const float2*)(bias + c);
    acc.x += bv.x; acc.y += bv.y;
    *(float2*)(out + (size_t)dst * DIM + c) = acc;
}

// ================= BN =========================================================
__global__ void zero_stats() {
    int i = threadIdx.x;
    if (i < DIM) { g_sum[i] = 0.f; g_sumsq[i] = 0.f; }
}

__global__ void bn_stats(const float* __restrict__ x, int n)
{
    int col = blockIdx.x * 256 + threadIdx.x;   // gridDim.x == 2
    float sm = 0.f, sq = 0.f;
    for (int r = blockIdx.y; r < n; r += gridDim.y) {
        float v = x[(size_t)r * DIM + col];
        sm += v;
        sq = fmaf(v, v, sq);
    }
    atomicAdd(&g_sum[col], sm);
    atomicAdd(&g_sumsq[col], sq);
}

__global__ void bn_apply(const float* __restrict__ x,
                         const float* __restrict__ gamma, const float* __restrict__ beta,
                         float* __restrict__ y, int n)
{
    int i = blockIdx.x * blockDim.x + threadIdx.x;
    if (i >= n * DIM) return;
    int col = i & (DIM - 1);
    float inv_n = 1.f / (float)n;
    float mu = g_sum[col] * inv_n;
    float var = g_sumsq[col] * inv_n - mu * mu;
    y[i] = fmaf(gamma[col] * (x[i] - mu), rsqrtf(var + 1e-5f), beta[col]);
}

// ================= final linear [512 -> 2] + relu =============================
__global__ void final_lin(const float* __restrict__ h, const float* __restrict__ w,
                          const float* __restrict__ b, float* __restrict__ out, int n)
{
    int warp = (blockIdx.x * blockDim.x + threadIdx.x) >> 5;
    int lane = threadIdx.x & 31;
    if (warp >= n) return;
    const float* row = h + (size_t)warp * DIM;
    float a0 = 0.f, a1 = 0.f;
#pragma unroll 4
    for (int c = lane; c < DIM; c += 32) {
        float v = row[c];
        a0 = fmaf(v, w[c * 2 + 0], a0);
        a1 = fmaf(v, w[c * 2 + 1], a1);
    }
#pragma unroll
    for (int o = 16; o; o >>= 1) {
        a0 += __shfl_down_sync(0xffffffffu, a0, o);
        a1 += __shfl_down_sync(0xffffffffu, a1, o);
    }
    if (lane == 0) {
        out[warp * 2 + 0] = fmaxf(a0 + b[0], 0.f);
        out[warp * 2 + 1] = fmaxf(a1 + b[1], 0.f);
    }
}

// ------------------------------------------------------------------------------
extern "C" void kernel_launch(void* const* d_in, const int* in_sizes, int n_in,
                              void* d_out, int out_size)
{
    const float* x    = (const float*)d_in[0];
    const int*   ei   = (const int*)d_in[1];     // int32 edge indices
    const float* W1   = (const float*)d_in[2];
    const float* a1s  = (const float*)d_in[3];
    const float* a1d  = (const float*)d_in[4];
    const float* b1   = (const float*)d_in[5];
    const float* W2   = (const float*)d_in[6];
    const float* a2s  = (const float*)d_in[7];
    const float* a2d  = (const float*)d_in[8];
    const float* b2   = (const float*)d_in[9];
    const float* fc1w = (const float*)d_in[10];
    const float* fc1b = (const float*)d_in[11];
    const float* g1   = (const float*)d_in[12];
    const float* be1  = (const float*)d_in[13];
    const float* fc2w = (const float*)d_in[14];
    const float* fc2b = (const float*)d_in[15];
    const float* g2   = (const float*)d_in[16];
    const float* be2  = (const float*)d_in[17];
    const float* linw = (const float*)d_in[18];
    const float* linb = (const float*)d_in[19];
    float* out = (float*)d_out;

    int n = out_size / 2;        // 20000
    int E = in_sizes[1] / 2;     // 320000
    int Et = E + n;

    float *A, *B, *C, *Dd, *als, *ald;
    cudaGetSymbolAddress((void**)&A,   g_bufA);
    cudaGetSymbolAddress((void**)&B,   g_bufB);
    cudaGetSymbolAddress((void**)&C,   g_bufC);
    cudaGetSymbolAddress((void**)&Dd,  g_bufD);
    cudaGetSymbolAddress((void**)&als, g_als);
    cudaGetSymbolAddress((void**)&ald, g_ald);

    dim3 gemm_grid(DIM / 128, (n + 127) / 128);
    int nd_blocks = (n * DIM + 255) / 256;

    // ---------------- CSR build (once, reused by both layers) ----------------
    csr_zero<<<(n + 255) / 256, 256>>>(n);
    csr_hist<<<(Et + 255) / 256, 256>>>(ei, E, n);
    csr_scan<<<1, 1024>>>(n, Et);
    csr_scatter<<<(Et + 255) / 256, 256>>>(ei, E, n);

    // ---------------- layer 1: GATConv(128 -> 8x64) ----------------
    gemm_bf16x3<<<gemm_grid, 256>>>(x, W1, nullptr, A, n, DIM, 128, 0, 0);
    attn_logits8<<<n, 256>>>(A, a1s, a1d, als, ald, n);
    gat_agg8<<<n, 256>>>(A, als, ald, b1, B);

    // ---------------- fc1 + relu + BN ----------------
    gemm_bf16x3<<<gemm_grid, 256>>>(B, fc1w, fc1b, C, n, DIM, DIM, 1, 1);
    zero_stats<<<1, 512>>>();
    bn_stats<<<dim3(2, 128), 256>>>(C, n);
    bn_apply<<<nd_blocks, 256>>>(C, g1, be1, Dd, n);

    // ---------------- layer 2: GATConv(512 -> 1x512) ----------------
    gemm_bf16x3<<<gemm_grid, 256>>>(Dd, W2, nullptr, A, n, DIM, DIM, 0, 0);
    attn_logits1<<<(n + 7) / 8, 256>>>(A, a2s, a2d, als, ald, n);
    gat_agg1<<<n, 256>>>(A, als, ald, b2, B);

    // ---------------- fc2 + relu + BN ----------------
    gemm_bf16x3<<<gemm_grid, 256>>>(B, fc2w, fc2b, C, n, DIM, DIM, 1, 1);
    zero_stats<<<1, 512>>>();
    bn_stats<<<dim3(2, 128), 256>>>(C, n);
    bn_apply<<<nd_blocks, 256>>>(C, g2, be2, Dd, n);

    // ---------------- final linear + relu ----------------
    final_lin<<<(n * 32 + 255) / 256, 256>>>(Dd, linw, linb, out, n);
}